// round 1
// baseline (speedup 1.0000x reference)
#include <cuda_runtime.h>
#include <math.h>
#include <stddef.h>

#define NN 100000
#define ME 800000
#define CC 1024
#define NCN 1000
#define HH 128
#define FEATD 140
#define OPCD 64
#define INDIM 205
#define CFGF 18
#define CHUNKC 512
#define EPSLN 1e-5f

// ---------------- static device scratch (no allocs allowed) ----------------
__device__ float g_h[(size_t)NN * HH];
__device__ float g_agg[(size_t)NN * HH];
__device__ int   g_deg[NN];
__device__ float g_invdeg[NN];
__device__ int   g_rowstart[NN + 1];
__device__ int   g_cursor[NN];
__device__ int   g_csr[ME];
__device__ int   g_bsum[128];
__device__ int   g_boff[128];
__device__ float g_proj[(size_t)NCN * CC * HH];   // 524 MB scratch
__device__ float g_gmean[HH];
__device__ float g_cfgemb[CC * HH];

__device__ __forceinline__ float gelu_f(float x) { return x * normcdff(x); }

// ---------------- init / degree / CSR build ----------------
__global__ void k_zero() {
    int i = blockIdx.x * 256 + threadIdx.x;
    if (i < NN) { g_deg[i] = 0; g_cursor[i] = 0; }
    if (i < CC * HH) g_cfgemb[i] = 0.f;
    if (i < HH) g_gmean[i] = 0.f;
}

__global__ void k_deg(const int* __restrict__ ei) {
    int e = blockIdx.x * 256 + threadIdx.x;
    if (e < ME) atomicAdd(&g_deg[ei[ME + e]], 1);
}

__global__ void k_scan1() {
    __shared__ int sa[1024], sb[1024];
    int t = threadIdx.x;
    int i = blockIdx.x * 1024 + t;
    int v = (i < NN) ? g_deg[i] : 0;
    sa[t] = v; __syncthreads();
    int* a = sa; int* b = sb;
    for (int off = 1; off < 1024; off <<= 1) {
        b[t] = a[t] + ((t >= off) ? a[t - off] : 0);
        __syncthreads();
        int* tmp = a; a = b; b = tmp;
    }
    if (i < NN) g_rowstart[i] = a[t];
    if (t == 1023) g_bsum[blockIdx.x] = a[t];
}

__global__ void k_scan2(int nblk) {
    if (threadIdx.x == 0) {
        int run = 0;
        for (int b = 0; b < nblk; b++) { g_boff[b] = run; run += g_bsum[b]; }
    }
}

__global__ void k_scan3() {
    int i = blockIdx.x * 256 + threadIdx.x;
    if (i < NN) {
        g_rowstart[i] = g_rowstart[i] + g_boff[i >> 10] - g_deg[i];
        g_invdeg[i] = 1.f / (float)max(g_deg[i], 1);
    }
    if (i == 0) g_rowstart[NN] = ME;
}

__global__ void k_fill(const int* __restrict__ ei) {
    int e = blockIdx.x * 256 + threadIdx.x;
    if (e < ME) {
        int d = ei[ME + e];
        int pos = g_rowstart[d] + atomicAdd(&g_cursor[d], 1);
        g_csr[pos] = ei[e];
    }
}

// ---------------- input embedding: concat -> linear -> LN -> GELU ----------------
__global__ __launch_bounds__(256) void k_input(
    const float* __restrict__ feat, const int* __restrict__ opcode,
    const float* __restrict__ depth, const float* __restrict__ emb,
    const float* __restrict__ w, const float* __restrict__ bias,
    const float* __restrict__ gg, const float* __restrict__ bb)
{
    extern __shared__ float sm[];
    float* sW = sm;                 // INDIM*HH
    float* sX = sm + INDIM * HH;    // 32*INDIM
    int tid = threadIdx.x;
    int n0 = blockIdx.x * 32;
    for (int idx = tid; idx < INDIM * HH; idx += 256) sW[idx] = w[idx];
    for (int idx = tid; idx < 32 * INDIM; idx += 256) {
        int r = idx / INDIM, k = idx - r * INDIM;
        int n = n0 + r;
        float v;
        if (k < FEATD) v = feat[(size_t)n * FEATD + k];
        else if (k < FEATD + OPCD) {
            int o = opcode[n]; o = min(max(o, 0), 119);
            v = emb[o * OPCD + (k - FEATD)];
        } else v = depth[n];
        sX[r * INDIM + k] = v;
    }
    __syncthreads();
    int q = tid >> 5, lane = tid & 31;
    float acc[16];
    #pragma unroll
    for (int z = 0; z < 16; z++) acc[z] = 0.f;
    #pragma unroll 4
    for (int k = 0; k < INDIM; k++) {
        float x0 = sX[(q * 4 + 0) * INDIM + k];
        float x1 = sX[(q * 4 + 1) * INDIM + k];
        float x2 = sX[(q * 4 + 2) * INDIM + k];
        float x3 = sX[(q * 4 + 3) * INDIM + k];
        #pragma unroll
        for (int i = 0; i < 4; i++) {
            float wv = sW[k * HH + lane + 32 * i];
            acc[0 + i]  += x0 * wv;
            acc[4 + i]  += x1 * wv;
            acc[8 + i]  += x2 * wv;
            acc[12 + i] += x3 * wv;
        }
    }
    #pragma unroll
    for (int r = 0; r < 4; r++) {
        float v[4];
        #pragma unroll
        for (int i = 0; i < 4; i++) v[i] = acc[r * 4 + i] + bias[lane + 32 * i];
        float s = v[0] + v[1] + v[2] + v[3];
        #pragma unroll
        for (int off = 16; off; off >>= 1) s += __shfl_xor_sync(0xffffffffu, s, off);
        float mu = s * (1.f / HH);
        float ss = 0.f;
        #pragma unroll
        for (int i = 0; i < 4; i++) { float d = v[i] - mu; ss += d * d; }
        #pragma unroll
        for (int off = 16; off; off >>= 1) ss += __shfl_xor_sync(0xffffffffu, ss, off);
        float rstd = rsqrtf(ss * (1.f / HH) + EPSLN);
        int n = n0 + q * 4 + r;
        #pragma unroll
        for (int i = 0; i < 4; i++) {
            int j = lane + 32 * i;
            float y = (v[i] - mu) * rstd * gg[j] + bb[j];
            g_h[(size_t)n * HH + j] = gelu_f(y);
        }
    }
}

// ---------------- mean aggregation over CSR neighbors ----------------
__global__ __launch_bounds__(256) void k_aggregate() {
    int wid = (blockIdx.x * 256 + threadIdx.x) >> 5;
    int lane = threadIdx.x & 31;
    if (wid >= NN) return;
    int s = g_rowstart[wid], e = g_rowstart[wid + 1];
    float4 acc = make_float4(0.f, 0.f, 0.f, 0.f);
    const float4* h4 = (const float4*)g_h;
    for (int p = s; p < e; p++) {
        int nb = g_csr[p];
        float4 v = h4[(size_t)nb * 32 + lane];
        acc.x += v.x; acc.y += v.y; acc.z += v.z; acc.w += v.w;
    }
    float inv = g_invdeg[wid];
    acc.x *= inv; acc.y *= inv; acc.z *= inv; acc.w *= inv;
    ((float4*)g_agg)[(size_t)wid * 32 + lane] = acc;
}

// ---------------- SAGE layer: conv = agg@Wl + bl + h@Wr; h = LN(h + gelu(conv)) ----------------
__global__ __launch_bounds__(256) void k_sage(
    const float* __restrict__ Wl, const float* __restrict__ bl,
    const float* __restrict__ Wr, const float* __restrict__ lng,
    const float* __restrict__ lnb)
{
    extern __shared__ float sm[];
    float* sWl = sm;
    float* sWr = sm + HH * HH;
    float* sA  = sm + 2 * HH * HH;           // 32*HH
    float* sH  = sm + 2 * HH * HH + 32 * HH; // 32*HH
    int tid = threadIdx.x;
    int n0 = blockIdx.x * 32;
    for (int idx = tid; idx < HH * HH; idx += 256) { sWl[idx] = Wl[idx]; sWr[idx] = Wr[idx]; }
    {
        const float4* a4 = (const float4*)(g_agg + (size_t)n0 * HH);
        const float4* h4 = (const float4*)(g_h + (size_t)n0 * HH);
        float4* sA4 = (float4*)sA; float4* sH4 = (float4*)sH;
        for (int idx = tid; idx < 32 * 32; idx += 256) { sA4[idx] = a4[idx]; sH4[idx] = h4[idx]; }
    }
    __syncthreads();
    int q = tid >> 5, lane = tid & 31;
    float acc[16];
    #pragma unroll
    for (int z = 0; z < 16; z++) acc[z] = 0.f;
    #pragma unroll 2
    for (int k = 0; k < HH; k++) {
        float a0 = sA[(q * 4 + 0) * HH + k], a1 = sA[(q * 4 + 1) * HH + k];
        float a2 = sA[(q * 4 + 2) * HH + k], a3 = sA[(q * 4 + 3) * HH + k];
        float h0 = sH[(q * 4 + 0) * HH + k], h1 = sH[(q * 4 + 1) * HH + k];
        float h2 = sH[(q * 4 + 2) * HH + k], h3 = sH[(q * 4 + 3) * HH + k];
        #pragma unroll
        for (int i = 0; i < 4; i++) {
            float wl = sWl[k * HH + lane + 32 * i];
            float wr = sWr[k * HH + lane + 32 * i];
            acc[0 + i]  = fmaf(a0, wl, fmaf(h0, wr, acc[0 + i]));
            acc[4 + i]  = fmaf(a1, wl, fmaf(h1, wr, acc[4 + i]));
            acc[8 + i]  = fmaf(a2, wl, fmaf(h2, wr, acc[8 + i]));
            acc[12 + i] = fmaf(a3, wl, fmaf(h3, wr, acc[12 + i]));
        }
    }
    #pragma unroll
    for (int r = 0; r < 4; r++) {
        float v[4];
        #pragma unroll
        for (int i = 0; i < 4; i++) {
            int j = lane + 32 * i;
            float c = acc[r * 4 + i] + bl[j];
            float g = gelu_f(c);
            v[i] = sH[(q * 4 + r) * HH + j] + g;
        }
        float s = v[0] + v[1] + v[2] + v[3];
        #pragma unroll
        for (int off = 16; off; off >>= 1) s += __shfl_xor_sync(0xffffffffu, s, off);
        float mu = s * (1.f / HH);
        float ss = 0.f;
        #pragma unroll
        for (int i = 0; i < 4; i++) { float d = v[i] - mu; ss += d * d; }
        #pragma unroll
        for (int off = 16; off; off >>= 1) ss += __shfl_xor_sync(0xffffffffu, ss, off);
        float rstd = rsqrtf(ss * (1.f / HH) + EPSLN);
        int n = n0 + q * 4 + r;
        #pragma unroll
        for (int i = 0; i < 4; i++) {
            int j = lane + 32 * i;
            g_h[(size_t)n * HH + j] = (v[i] - mu) * rstd * lng[j] + lnb[j];
        }
    }
}

// ---------------- global mean of h ----------------
__global__ __launch_bounds__(256) void k_gmean() {
    __shared__ float sG[2][HH];
    int j = threadIdx.x & 127, half = threadIdx.x >> 7;
    int n0 = blockIdx.x * 400;
    float s = 0.f;
    for (int n = n0 + half; n < n0 + 400; n += 2) s += g_h[(size_t)n * HH + j];
    sG[half][j] = s; __syncthreads();
    if (threadIdx.x < HH) atomicAdd(&g_gmean[threadIdx.x], sG[0][threadIdx.x] + sG[1][threadIdx.x]);
}

// ---------------- pass A: proj = gelu(combined@cfg_w + b); SE scale; store ----------------
__global__ __launch_bounds__(256) void k_passA(
    const int* __restrict__ cfg_ids, const float* __restrict__ cfg_feat,
    const float* __restrict__ cw, const float* __restrict__ cb,
    const float* __restrict__ s1w, const float* __restrict__ s1b,
    const float* __restrict__ s2w, const float* __restrict__ s2b)
{
    extern __shared__ float sm[];
    float* sW2   = sm;                    // CFGF*HH
    float* sS1   = sW2 + CFGF * HH;       // HH*16
    float* sS2   = sS1 + HH * 16;         // 16*HH
    float* sF    = sS2 + 16 * HH;         // 256*CFGF
    float* sBase = sF + 256 * CFGF;       // HH
    float* sHr   = sBase + HH;            // HH
    float* sB1   = sHr + HH;              // 16
    float* sB2   = sB1 + 16;              // HH
    float* sP    = sB2 + HH;              // 8*HH
    float* sSb   = sP + 8 * HH;           // 8*16
    int tid = threadIdx.x;
    int ct = blockIdx.x, nc = blockIdx.y;
    int nid = cfg_ids[nc];
    if (tid < HH) sHr[tid] = g_h[(size_t)nid * HH + tid];
    for (int idx = tid; idx < CFGF * HH; idx += 256) sW2[idx] = cw[HH * HH + idx];
    for (int idx = tid; idx < HH * 16; idx += 256) sS1[idx] = s1w[idx];
    for (int idx = tid; idx < 16 * HH; idx += 256) sS2[idx] = s2w[idx];
    if (tid < 16) sB1[tid] = s1b[tid];
    if (tid < HH) sB2[tid] = s2b[tid];
    for (int idx = tid; idx < 256 * CFGF; idx += 256) {
        int r = idx / CFGF, k = idx - r * CFGF;
        int c = ct * 256 + r;
        sF[idx] = cfg_feat[((size_t)c * NCN + nc) * CFGF + k];
    }
    __syncthreads();
    // base[j] = h_row @ cfg_w_top + cfg_b   (shared across all configs of this nc)
    {
        int j = tid & 127, half = tid >> 7;
        float s = 0.f;
        for (int k = half * 64; k < half * 64 + 64; k++) s += sHr[k] * cw[k * HH + j];
        sP[half * HH + j] = s;
        __syncthreads();
        if (tid < HH) sBase[tid] = sP[tid] + sP[HH + tid] + cb[tid];
        __syncthreads();
    }
    int w = tid >> 5, lane = tid & 31;
    float* pr = sP + w * HH;
    for (int it = 0; it < 32; it++) {
        int r = w * 32 + it;
        float p[4];
        #pragma unroll
        for (int i = 0; i < 4; i++) p[i] = sBase[lane + 32 * i];
        #pragma unroll
        for (int k = 0; k < CFGF; k++) {
            float f = sF[r * CFGF + k];
            #pragma unroll
            for (int i = 0; i < 4; i++) p[i] += f * sW2[k * HH + lane + 32 * i];
        }
        #pragma unroll
        for (int i = 0; i < 4; i++) p[i] = gelu_f(p[i]);
        #pragma unroll
        for (int i = 0; i < 4; i++) pr[lane + 32 * i] = p[i];
        __syncwarp();
        int m = lane & 15, jh = lane >> 4;
        float s = 0.f;
        #pragma unroll
        for (int k = 0; k < 64; k++) s += pr[jh * 64 + k] * sS1[(jh * 64 + k) * 16 + m];
        s += __shfl_xor_sync(0xffffffffu, s, 16);
        s = fmaxf(s + sB1[m], 0.f);
        if (lane < 16) sSb[w * 16 + lane] = s;
        __syncwarp();
        size_t obase = ((size_t)nc * CC + ct * 256 + r) * HH;
        #pragma unroll
        for (int i = 0; i < 4; i++) {
            int j = lane + 32 * i;
            float sc = sB2[j];
            #pragma unroll
            for (int m2 = 0; m2 < 16; m2++) sc += sSb[w * 16 + m2] * sS2[m2 * HH + j];
            sc = 1.f / (1.f + __expf(-sc));
            g_proj[obase + j] = p[i] * sc;
        }
        __syncwarp();
    }
}

// ---------------- pass B: chunked softmax over configs, weight, mean over nc ----------------
__global__ __launch_bounds__(512) void k_passB(const float* __restrict__ temp) {
    __shared__ float sR[16][32];
    int tid = threadIdx.x;
    int j32 = tid & 31, strip = tid >> 5;
    int bx = blockIdx.x;
    int grp = bx >> 3;
    int chunk = bx & 1, jt = (bx >> 1) & 3;
    int j = jt * 32 + j32;
    float invT = 1.f / temp[0];
    float acc[32];
    #pragma unroll
    for (int k = 0; k < 32; k++) acc[k] = 0.f;
    int cbase = chunk * CHUNKC + strip * 32;
    for (int nc = grp * 25; nc < grp * 25 + 25; nc++) {
        float x[32];
        size_t p0 = ((size_t)nc * CC + cbase) * HH + j;
        #pragma unroll
        for (int k = 0; k < 32; k++) x[k] = g_proj[p0 + (size_t)k * HH];
        float m = -1e30f;
        #pragma unroll
        for (int k = 0; k < 32; k++) m = fmaxf(m, x[k]);
        sR[strip][j32] = m; __syncthreads();
        float M = -1e30f;
        #pragma unroll
        for (int s2 = 0; s2 < 16; s2++) M = fmaxf(M, sR[s2][j32]);
        __syncthreads();
        float se = 0.f;
        #pragma unroll
        for (int k = 0; k < 32; k++) se += __expf((x[k] - M) * invT);
        sR[strip][j32] = se; __syncthreads();
        float S = 0.f;
        #pragma unroll
        for (int s2 = 0; s2 < 16; s2++) S += sR[s2][j32];
        __syncthreads();
        float inv = 1.f / S;
        #pragma unroll
        for (int k = 0; k < 32; k++) acc[k] += x[k] * __expf((x[k] - M) * invT) * inv;
    }
    #pragma unroll
    for (int k = 0; k < 32; k++)
        atomicAdd(&g_cfgemb[(cbase + k) * HH + j], acc[k]);
}

// ---------------- head MLP ----------------
__global__ __launch_bounds__(128) void k_head(
    const float* __restrict__ w1, const float* __restrict__ b1,
    const float* __restrict__ w2, const float* __restrict__ b2,
    const float* __restrict__ w3, const float* __restrict__ b3,
    float* __restrict__ out)
{
    __shared__ float sin[256], sx1[128], sx2[64], sred[64];
    int c = blockIdx.x, tid = threadIdx.x;
    sin[tid] = g_gmean[tid] * (1.f / NN);
    sin[128 + tid] = g_cfgemb[c * HH + tid] * (1.f / NCN);
    __syncthreads();
    float a = b1[tid];
    #pragma unroll 4
    for (int k = 0; k < 256; k++) a += sin[k] * w1[k * HH + tid];
    sx1[tid] = gelu_f(a);
    __syncthreads();
    if (tid < 64) {
        float a2 = b2[tid];
        #pragma unroll 4
        for (int k = 0; k < HH; k++) a2 += sx1[k] * w2[k * 64 + tid];
        sx2[tid] = gelu_f(a2);
    }
    __syncthreads();
    if (tid < 64) sred[tid] = sx2[tid] * w3[tid];
    __syncthreads();
    if (tid < 32) sred[tid] += sred[tid + 32]; __syncthreads();
    if (tid < 16) sred[tid] += sred[tid + 16]; __syncthreads();
    if (tid < 8)  sred[tid] += sred[tid + 8];  __syncthreads();
    if (tid < 4)  sred[tid] += sred[tid + 4];  __syncthreads();
    if (tid < 2)  sred[tid] += sred[tid + 2];  __syncthreads();
    if (tid == 0) out[c] = sred[0] + sred[1] + b3[0];
}

// ---------------- launcher ----------------
extern "C" void kernel_launch(void* const* d_in, const int* in_sizes, int n_in,
                              void* d_out, int out_size) {
    const float* node_feat    = (const float*)d_in[0];
    const int*   node_opcode  = (const int*)d_in[1];
    const float* topo_depth   = (const float*)d_in[2];
    const int*   edge_index   = (const int*)d_in[3];
    const int*   config_ids   = (const int*)d_in[4];
    const float* config_feat  = (const float*)d_in[5];
    const float* temperature  = (const float*)d_in[6];
    const float* opcode_embed = (const float*)d_in[7];
    const float* in_w   = (const float*)d_in[8];
    const float* in_b   = (const float*)d_in[9];
    const float* in_g   = (const float*)d_in[10];
    const float* in_beta= (const float*)d_in[11];
    const float* sage_Wl= (const float*)d_in[12];
    const float* sage_bl= (const float*)d_in[13];
    const float* sage_Wr= (const float*)d_in[14];
    const float* ln_g   = (const float*)d_in[15];
    const float* ln_b   = (const float*)d_in[16];
    const float* cfg_w  = (const float*)d_in[17];
    const float* cfg_b  = (const float*)d_in[18];
    const float* se_w1  = (const float*)d_in[19];
    const float* se_b1  = (const float*)d_in[20];
    const float* se_w2  = (const float*)d_in[21];
    const float* se_b2  = (const float*)d_in[22];
    const float* h_w1   = (const float*)d_in[23];
    const float* h_b1   = (const float*)d_in[24];
    const float* h_w2   = (const float*)d_in[25];
    const float* h_b2   = (const float*)d_in[26];
    const float* h_w3   = (const float*)d_in[27];
    const float* h_b3   = (const float*)d_in[28];
    float* out = (float*)d_out;

    cudaFuncSetAttribute(k_input, cudaFuncAttributeMaxDynamicSharedMemorySize, (INDIM * HH + 32 * INDIM) * 4);
    cudaFuncSetAttribute(k_sage,  cudaFuncAttributeMaxDynamicSharedMemorySize, (2 * HH * HH + 64 * HH) * 4);
    cudaFuncSetAttribute(k_passA, cudaFuncAttributeMaxDynamicSharedMemorySize, 50240);

    k_zero<<<(CC * HH + 255) / 256, 256>>>();
    k_deg<<<(ME + 255) / 256, 256>>>(edge_index);
    k_scan1<<<98, 1024>>>();
    k_scan2<<<1, 32>>>(98);
    k_scan3<<<(NN + 255) / 256, 256>>>();
    k_fill<<<(ME + 255) / 256, 256>>>(edge_index);
    k_input<<<NN / 32, 256, (INDIM * HH + 32 * INDIM) * 4>>>(
        node_feat, node_opcode, topo_depth, opcode_embed, in_w, in_b, in_g, in_beta);
    for (int l = 0; l < 4; l++) {
        k_aggregate<<<NN / 8, 256>>>();
        k_sage<<<NN / 32, 256, (2 * HH * HH + 64 * HH) * 4>>>(
            sage_Wl + (size_t)l * HH * HH, sage_bl + l * HH,
            sage_Wr + (size_t)l * HH * HH, ln_g + l * HH, ln_b + l * HH);
    }
    k_gmean<<<250, 256>>>();
    dim3 ga(4, 1000);
    k_passA<<<ga, 256, 50240>>>(config_ids, config_feat, cfg_w, cfg_b,
                                se_w1, se_b1, se_w2, se_b2);
    k_passB<<<320, 512>>>(temperature);
    k_head<<<CC, 128>>>(h_w1, h_b1, h_w2, h_b2, h_w3, h_b3, out);
}

// round 3
// speedup vs baseline: 1.1009x; 1.1009x over previous
#include <cuda_runtime.h>
#include <math.h>
#include <stddef.h>

#define NN 100000
#define ME 800000
#define CC 1024
#define NCN 1000
#define HH 128
#define FEATD 140
#define OPCD 64
#define INDIM 205
#define CFGF 18
#define CHUNKC 512
#define EPSLN 1e-5f

// ---------------- static device scratch ----------------
__device__ float g_h[(size_t)NN * HH];
__device__ float g_agg[(size_t)NN * HH];
__device__ int   g_deg[NN];
__device__ float g_invdeg[NN];
__device__ int   g_rowstart[NN + 1];
__device__ int   g_cursor[NN];
__device__ int   g_csr[ME];
__device__ int   g_bsum[128];
__device__ int   g_boff[128];
__device__ float g_proj[(size_t)NCN * CC * HH];
__device__ float g_gmean[HH];
__device__ float g_cfgemb[CC * HH];

__device__ __forceinline__ float gelu_f(float x) { return x * normcdff(x); }

// ---------------- init / degree / CSR build ----------------
__global__ void k_zero() {
    int i = blockIdx.x * 256 + threadIdx.x;
    if (i < NN) { g_deg[i] = 0; g_cursor[i] = 0; }
    if (i < CC * HH) g_cfgemb[i] = 0.f;
    if (i < HH) g_gmean[i] = 0.f;
}

__global__ void k_deg(const int* __restrict__ ei) {
    int e = blockIdx.x * 256 + threadIdx.x;
    if (e < ME) atomicAdd(&g_deg[ei[ME + e]], 1);
}

__global__ void k_scan1() {
    __shared__ int sa[1024], sb[1024];
    int t = threadIdx.x;
    int i = blockIdx.x * 1024 + t;
    int v = (i < NN) ? g_deg[i] : 0;
    sa[t] = v; __syncthreads();
    int* a = sa; int* b = sb;
    for (int off = 1; off < 1024; off <<= 1) {
        b[t] = a[t] + ((t >= off) ? a[t - off] : 0);
        __syncthreads();
        int* tmp = a; a = b; b = tmp;
    }
    if (i < NN) g_rowstart[i] = a[t];
    if (t == 1023) g_bsum[blockIdx.x] = a[t];
}

__global__ void k_scan2(int nblk) {
    __shared__ int ws[4];
    int t = threadIdx.x;
    int orig = (t < nblk) ? g_bsum[t] : 0;
    int v = orig;
    #pragma unroll
    for (int off = 1; off < 32; off <<= 1) {
        int u = __shfl_up_sync(0xffffffffu, v, off);
        if ((t & 31) >= off) v += u;
    }
    if ((t & 31) == 31) ws[t >> 5] = v;
    __syncthreads();
    int add = 0;
    for (int wv = 0; wv < (t >> 5); wv++) add += ws[wv];
    v += add;
    if (t < nblk) g_boff[t] = v - orig;
}

__global__ void k_scan3() {
    int i = blockIdx.x * 256 + threadIdx.x;
    if (i < NN) {
        g_rowstart[i] = g_rowstart[i] + g_boff[i >> 10] - g_deg[i];
        g_invdeg[i] = 1.f / (float)max(g_deg[i], 1);
    }
    if (i == 0) g_rowstart[NN] = ME;
}

__global__ void k_fill(const int* __restrict__ ei) {
    int e = blockIdx.x * 256 + threadIdx.x;
    if (e < ME) {
        int d = ei[ME + e];
        int pos = g_rowstart[d] + atomicAdd(&g_cursor[d], 1);
        g_csr[pos] = ei[e];
    }
}

// ---------------- input embedding: concat -> linear -> LN -> GELU ----------------
// 512 threads, 32 nodes/block. Thread: 2 nodes x 4 consecutive cols.
__global__ __launch_bounds__(512) void k_input(
    const float* __restrict__ feat, const int* __restrict__ opcode,
    const float* __restrict__ depth, const float* __restrict__ emb,
    const float* __restrict__ w, const float* __restrict__ bias,
    const float* __restrict__ gg, const float* __restrict__ bb)
{
    extern __shared__ float sm[];
    float* sW = sm;                 // INDIM*HH
    float* sX = sm + INDIM * HH;    // 32*INDIM
    int tid = threadIdx.x;
    int n0 = blockIdx.x * 32;
    {
        float4* sW4 = (float4*)sW;
        const float4* w4 = (const float4*)w;
        for (int idx = tid; idx < INDIM * HH / 4; idx += 512) sW4[idx] = w4[idx];
    }
    for (int idx = tid; idx < 32 * INDIM; idx += 512) {
        int r = idx / INDIM, k = idx - r * INDIM;
        int n = n0 + r;
        float v = 0.f;
        if (n < NN) {
            if (k < FEATD) v = feat[(size_t)n * FEATD + k];
            else if (k < FEATD + OPCD) {
                int o = opcode[n]; o = min(max(o, 0), 119);
                v = emb[o * OPCD + (k - FEATD)];
            } else v = depth[n];
        }
        sX[r * INDIM + k] = v;
    }
    __syncthreads();
    int w5 = tid >> 5, lane = tid & 31;
    int c0 = lane * 4;
    int r0 = w5 * 2;
    float acc[8];
    #pragma unroll
    for (int z = 0; z < 8; z++) acc[z] = 0.f;
    for (int k = 0; k < INDIM; k++) {
        const float4 wv = *(const float4*)(sW + k * HH + c0);
        #pragma unroll
        for (int i = 0; i < 2; i++) {
            float x = sX[(r0 + i) * INDIM + k];
            acc[i * 4 + 0] = fmaf(x, wv.x, acc[i * 4 + 0]);
            acc[i * 4 + 1] = fmaf(x, wv.y, acc[i * 4 + 1]);
            acc[i * 4 + 2] = fmaf(x, wv.z, acc[i * 4 + 2]);
            acc[i * 4 + 3] = fmaf(x, wv.w, acc[i * 4 + 3]);
        }
    }
    const float4 bi = *(const float4*)(bias + c0);
    const float4 gv = *(const float4*)(gg + c0);
    const float4 bv = *(const float4*)(bb + c0);
    #pragma unroll
    for (int i = 0; i < 2; i++) {
        float v[4];
        v[0] = acc[i * 4 + 0] + bi.x; v[1] = acc[i * 4 + 1] + bi.y;
        v[2] = acc[i * 4 + 2] + bi.z; v[3] = acc[i * 4 + 3] + bi.w;
        float s = v[0] + v[1] + v[2] + v[3];
        #pragma unroll
        for (int off = 16; off; off >>= 1) s += __shfl_xor_sync(0xffffffffu, s, off);
        float mu = s * (1.f / HH);
        float ss = 0.f;
        #pragma unroll
        for (int j = 0; j < 4; j++) { float d = v[j] - mu; ss += d * d; }
        #pragma unroll
        for (int off = 16; off; off >>= 1) ss += __shfl_xor_sync(0xffffffffu, ss, off);
        float rstd = rsqrtf(ss * (1.f / HH) + EPSLN);
        int n = n0 + r0 + i;
        if (n < NN) {
            float4 o;
            o.x = gelu_f((v[0] - mu) * rstd * gv.x + bv.x);
            o.y = gelu_f((v[1] - mu) * rstd * gv.y + bv.y);
            o.z = gelu_f((v[2] - mu) * rstd * gv.z + bv.z);
            o.w = gelu_f((v[3] - mu) * rstd * gv.w + bv.w);
            ((float4*)g_h)[(size_t)n * 32 + lane] = o;
        }
    }
}

// ---------------- mean aggregation over CSR neighbors ----------------
__global__ __launch_bounds__(256) void k_aggregate() {
    int wid = (blockIdx.x * 256 + threadIdx.x) >> 5;
    int lane = threadIdx.x & 31;
    if (wid >= NN) return;
    int s = g_rowstart[wid], e = g_rowstart[wid + 1];
    float4 acc = make_float4(0.f, 0.f, 0.f, 0.f);
    float4 acc2 = make_float4(0.f, 0.f, 0.f, 0.f);
    const float4* h4 = (const float4*)g_h;
    int p = s;
    for (; p + 1 < e; p += 2) {
        int nb0 = g_csr[p], nb1 = g_csr[p + 1];
        float4 v0 = h4[(size_t)nb0 * 32 + lane];
        float4 v1 = h4[(size_t)nb1 * 32 + lane];
        acc.x += v0.x; acc.y += v0.y; acc.z += v0.z; acc.w += v0.w;
        acc2.x += v1.x; acc2.y += v1.y; acc2.z += v1.z; acc2.w += v1.w;
    }
    if (p < e) {
        int nb = g_csr[p];
        float4 v = h4[(size_t)nb * 32 + lane];
        acc.x += v.x; acc.y += v.y; acc.z += v.z; acc.w += v.w;
    }
    float inv = g_invdeg[wid];
    acc.x = (acc.x + acc2.x) * inv; acc.y = (acc.y + acc2.y) * inv;
    acc.z = (acc.z + acc2.z) * inv; acc.w = (acc.w + acc2.w) * inv;
    ((float4*)g_agg)[(size_t)wid * 32 + lane] = acc;
}

// ---------------- SAGE layer ----------------
// 512 threads, 32 nodes/block. Thread: 2 nodes x 4 consecutive cols.
// smem = 2*HH*HH (weights) + 2*32*HH (acts) = 128KB + 32KB = 160KB
__global__ __launch_bounds__(512) void k_sage(
    const float* __restrict__ Wl, const float* __restrict__ bl,
    const float* __restrict__ Wr, const float* __restrict__ lng,
    const float* __restrict__ lnb)
{
    extern __shared__ float sm[];
    float* sWl = sm;                          // HH*HH
    float* sWr = sm + HH * HH;                // HH*HH
    float* sA  = sm + 2 * HH * HH;            // 32*HH
    float* sH  = sm + 2 * HH * HH + 32 * HH;  // 32*HH
    int tid = threadIdx.x;
    int n0 = blockIdx.x * 32;
    {
        float4* l4 = (float4*)sWl; float4* r4 = (float4*)sWr;
        const float4* Wl4 = (const float4*)Wl; const float4* Wr4 = (const float4*)Wr;
        for (int idx = tid; idx < HH * HH / 4; idx += 512) { l4[idx] = Wl4[idx]; r4[idx] = Wr4[idx]; }
    }
    {
        float4* sA4 = (float4*)sA; float4* sH4 = (float4*)sH;
        const float4* a4 = (const float4*)(g_agg + (size_t)n0 * HH);
        const float4* h4 = (const float4*)(g_h + (size_t)n0 * HH);
        for (int idx = tid; idx < 32 * 32; idx += 512) {
            int r = idx >> 5;
            if (n0 + r < NN) { sA4[idx] = a4[idx]; sH4[idx] = h4[idx]; }
            else { sA4[idx] = make_float4(0, 0, 0, 0); sH4[idx] = make_float4(0, 0, 0, 0); }
        }
    }
    __syncthreads();
    int w5 = tid >> 5, lane = tid & 31;
    int c0 = lane * 4;
    int r0 = w5 * 2;
    float acc[8];
    #pragma unroll
    for (int z = 0; z < 8; z++) acc[z] = 0.f;
    #pragma unroll 2
    for (int k = 0; k < HH; k++) {
        const float4 wl = *(const float4*)(sWl + k * HH + c0);
        const float4 wr = *(const float4*)(sWr + k * HH + c0);
        #pragma unroll
        for (int i = 0; i < 2; i++) {
            float a = sA[(r0 + i) * HH + k];
            float h = sH[(r0 + i) * HH + k];
            acc[i * 4 + 0] = fmaf(a, wl.x, fmaf(h, wr.x, acc[i * 4 + 0]));
            acc[i * 4 + 1] = fmaf(a, wl.y, fmaf(h, wr.y, acc[i * 4 + 1]));
            acc[i * 4 + 2] = fmaf(a, wl.z, fmaf(h, wr.z, acc[i * 4 + 2]));
            acc[i * 4 + 3] = fmaf(a, wl.w, fmaf(h, wr.w, acc[i * 4 + 3]));
        }
    }
    const float4 bi = *(const float4*)(bl + c0);
    const float4 gv = *(const float4*)(lng + c0);
    const float4 bv = *(const float4*)(lnb + c0);
    #pragma unroll
    for (int i = 0; i < 2; i++) {
        float v[4];
        #pragma unroll
        for (int j = 0; j < 4; j++) {
            float c = acc[i * 4 + j] + ((const float*)&bi)[j];
            v[j] = sH[(r0 + i) * HH + c0 + j] + gelu_f(c);
        }
        float s = v[0] + v[1] + v[2] + v[3];
        #pragma unroll
        for (int off = 16; off; off >>= 1) s += __shfl_xor_sync(0xffffffffu, s, off);
        float mu = s * (1.f / HH);
        float ss = 0.f;
        #pragma unroll
        for (int j = 0; j < 4; j++) { float d = v[j] - mu; ss += d * d; }
        #pragma unroll
        for (int off = 16; off; off >>= 1) ss += __shfl_xor_sync(0xffffffffu, ss, off);
        float rstd = rsqrtf(ss * (1.f / HH) + EPSLN);
        int n = n0 + r0 + i;
        if (n < NN) {
            float4 o;
            o.x = (v[0] - mu) * rstd * gv.x + bv.x;
            o.y = (v[1] - mu) * rstd * gv.y + bv.y;
            o.z = (v[2] - mu) * rstd * gv.z + bv.z;
            o.w = (v[3] - mu) * rstd * gv.w + bv.w;
            ((float4*)g_h)[(size_t)n * 32 + lane] = o;
        }
    }
}

// ---------------- global mean of h ----------------
__global__ __launch_bounds__(256) void k_gmean() {
    __shared__ float sG[2][HH];
    int j = threadIdx.x & 127, half = threadIdx.x >> 7;
    int n0 = blockIdx.x * 400;
    float s = 0.f;
    for (int n = n0 + half; n < n0 + 400; n += 2) s += g_h[(size_t)n * HH + j];
    sG[half][j] = s; __syncthreads();
    if (threadIdx.x < HH) atomicAdd(&g_gmean[threadIdx.x], sG[0][threadIdx.x] + sG[1][threadIdx.x]);
}

// ---------------- pass A ----------------
__global__ __launch_bounds__(256) void k_passA(
    const int* __restrict__ cfg_ids, const float* __restrict__ cfg_feat,
    const float* __restrict__ cw, const float* __restrict__ cb,
    const float* __restrict__ s1w, const float* __restrict__ s1b,
    const float* __restrict__ s2w, const float* __restrict__ s2b)
{
    extern __shared__ float sm[];
    float* sW2   = sm;                    // CFGF*HH
    float* sS1   = sW2 + CFGF * HH;       // HH*16
    float* sS2   = sS1 + HH * 16;         // 16*HH
    float* sF    = sS2 + 16 * HH;         // 256*CFGF
    float* sBase = sF + 256 * CFGF;       // HH
    float* sHr   = sBase + HH;            // HH
    float* sB1   = sHr + HH;              // 16
    float* sB2   = sB1 + 16;              // HH
    float* sP    = sB2 + HH;              // 8*HH
    float* sSb   = sP + 8 * HH;           // 8*16
    int tid = threadIdx.x;
    int ct = blockIdx.x, nc = blockIdx.y;
    int nid = cfg_ids[nc];
    if (tid < HH) sHr[tid] = g_h[(size_t)nid * HH + tid];
    for (int idx = tid; idx < CFGF * HH; idx += 256) sW2[idx] = cw[HH * HH + idx];
    for (int idx = tid; idx < HH * 16; idx += 256) sS1[idx] = s1w[idx];
    for (int idx = tid; idx < 16 * HH; idx += 256) sS2[idx] = s2w[idx];
    if (tid < 16) sB1[tid] = s1b[tid];
    if (tid < HH) sB2[tid] = s2b[tid];
    for (int idx = tid; idx < 256 * CFGF; idx += 256) {
        int r = idx / CFGF, k = idx - r * CFGF;
        int c = ct * 256 + r;
        sF[idx] = cfg_feat[((size_t)c * NCN + nc) * CFGF + k];
    }
    __syncthreads();
    {
        int j = tid & 127, half = tid >> 7;
        float s = 0.f;
        for (int k = half * 64; k < half * 64 + 64; k++) s += sHr[k] * cw[k * HH + j];
        sP[half * HH + j] = s;
        __syncthreads();
        if (tid < HH) sBase[tid] = sP[tid] + sP[HH + tid] + cb[tid];
        __syncthreads();
    }
    int w = tid >> 5, lane = tid & 31;
    float* pr = sP + w * HH;
    for (int it = 0; it < 32; it++) {
        int r = w * 32 + it;
        float p[4];
        #pragma unroll
        for (int i = 0; i < 4; i++) p[i] = sBase[lane + 32 * i];
        #pragma unroll
        for (int k = 0; k < CFGF; k++) {
            float f = sF[r * CFGF + k];
            #pragma unroll
            for (int i = 0; i < 4; i++) p[i] += f * sW2[k * HH + lane + 32 * i];
        }
        #pragma unroll
        for (int i = 0; i < 4; i++) p[i] = gelu_f(p[i]);
        #pragma unroll
        for (int i = 0; i < 4; i++) pr[lane + 32 * i] = p[i];
        __syncwarp();
        int m = lane & 15, jh = lane >> 4;
        float s = 0.f;
        #pragma unroll
        for (int k = 0; k < 64; k++) s += pr[jh * 64 + k] * sS1[(jh * 64 + k) * 16 + m];
        s += __shfl_xor_sync(0xffffffffu, s, 16);
        s = fmaxf(s + sB1[m], 0.f);
        if (lane < 16) sSb[w * 16 + lane] = s;
        __syncwarp();
        size_t obase = ((size_t)nc * CC + ct * 256 + r) * HH;
        #pragma unroll
        for (int i = 0; i < 4; i++) {
            int j = lane + 32 * i;
            float sc = sB2[j];
            #pragma unroll
            for (int m2 = 0; m2 < 16; m2++) sc += sSb[w * 16 + m2] * sS2[m2 * HH + j];
            sc = 1.f / (1.f + __expf(-sc));
            g_proj[obase + j] = p[i] * sc;
        }
        __syncwarp();
    }
}

// ---------------- pass B ----------------
__global__ __launch_bounds__(512) void k_passB(const float* __restrict__ temp) {
    __shared__ float sR[16][32];
    int tid = threadIdx.x;
    int j32 = tid & 31, strip = tid >> 5;
    int bx = blockIdx.x;
    int grp = bx >> 3;
    int chunk = bx & 1, jt = (bx >> 1) & 3;
    int j = jt * 32 + j32;
    float invT = 1.f / temp[0];
    float acc[32];
    #pragma unroll
    for (int k = 0; k < 32; k++) acc[k] = 0.f;
    int cbase = chunk * CHUNKC + strip * 32;
    for (int nc = grp * 25; nc < grp * 25 + 25; nc++) {
        float x[32];
        size_t p0 = ((size_t)nc * CC + cbase) * HH + j;
        #pragma unroll
        for (int k = 0; k < 32; k++) x[k] = g_proj[p0 + (size_t)k * HH];
        float m = -1e30f;
        #pragma unroll
        for (int k = 0; k < 32; k++) m = fmaxf(m, x[k]);
        sR[strip][j32] = m; __syncthreads();
        float M = -1e30f;
        #pragma unroll
        for (int s2 = 0; s2 < 16; s2++) M = fmaxf(M, sR[s2][j32]);
        __syncthreads();
        float e[32];
        float se = 0.f;
        #pragma unroll
        for (int k = 0; k < 32; k++) { e[k] = __expf((x[k] - M) * invT); se += e[k]; }
        sR[strip][j32] = se; __syncthreads();
        float S = 0.f;
        #pragma unroll
        for (int s2 = 0; s2 < 16; s2++) S += sR[s2][j32];
        __syncthreads();
        float inv = 1.f / S;
        #pragma unroll
        for (int k = 0; k < 32; k++) acc[k] += x[k] * e[k] * inv;
    }
    #pragma unroll
    for (int k = 0; k < 32; k++)
        atomicAdd(&g_cfgemb[(cbase + k) * HH + j], acc[k]);
}

// ---------------- head MLP ----------------
__global__ __launch_bounds__(128) void k_head(
    const float* __restrict__ w1, const float* __restrict__ b1,
    const float* __restrict__ w2, const float* __restrict__ b2,
    const float* __restrict__ w3, const float* __restrict__ b3,
    float* __restrict__ out)
{
    __shared__ float sin[256], sx1[128], sx2[64], sred[64];
    int c = blockIdx.x, tid = threadIdx.x;
    sin[tid] = g_gmean[tid] * (1.f / NN);
    sin[128 + tid] = g_cfgemb[c * HH + tid] * (1.f / NCN);
    __syncthreads();
    float a = b1[tid];
    #pragma unroll 4
    for (int k = 0; k < 256; k++) a += sin[k] * w1[k * HH + tid];
    sx1[tid] = gelu_f(a);
    __syncthreads();
    if (tid < 64) {
        float a2 = b2[tid];
        #pragma unroll 4
        for (int k = 0; k < HH; k++) a2 += sx1[k] * w2[k * 64 + tid];
        sx2[tid] = gelu_f(a2);
    }
    __syncthreads();
    if (tid < 64) sred[tid] = sx2[tid] * w3[tid];
    __syncthreads();
    if (tid < 32) sred[tid] += sred[tid + 32]; __syncthreads();
    if (tid < 16) sred[tid] += sred[tid + 16]; __syncthreads();
    if (tid < 8)  sred[tid] += sred[tid + 8];  __syncthreads();
    if (tid < 4)  sred[tid] += sred[tid + 4];  __syncthreads();
    if (tid < 2)  sred[tid] += sred[tid + 2];  __syncthreads();
    if (tid == 0) out[c] = sred[0] + sred[1] + b3[0];
}

// ---------------- launcher ----------------
extern "C" void kernel_launch(void* const* d_in, const int* in_sizes, int n_in,
                              void* d_out, int out_size) {
    const float* node_feat    = (const float*)d_in[0];
    const int*   node_opcode  = (const int*)d_in[1];
    const float* topo_depth   = (const float*)d_in[2];
    const int*   edge_index   = (const int*)d_in[3];
    const int*   config_ids   = (const int*)d_in[4];
    const float* config_feat  = (const float*)d_in[5];
    const float* temperature  = (const float*)d_in[6];
    const float* opcode_embed = (const float*)d_in[7];
    const float* in_w   = (const float*)d_in[8];
    const float* in_b   = (const float*)d_in[9];
    const float* in_g   = (const float*)d_in[10];
    const float* in_beta= (const float*)d_in[11];
    const float* sage_Wl= (const float*)d_in[12];
    const float* sage_bl= (const float*)d_in[13];
    const float* sage_Wr= (const float*)d_in[14];
    const float* ln_g   = (const float*)d_in[15];
    const float* ln_b   = (const float*)d_in[16];
    const float* cfg_w  = (const float*)d_in[17];
    const float* cfg_b  = (const float*)d_in[18];
    const float* se_w1  = (const float*)d_in[19];
    const float* se_b1  = (const float*)d_in[20];
    const float* se_w2  = (const float*)d_in[21];
    const float* se_b2  = (const float*)d_in[22];
    const float* h_w1   = (const float*)d_in[23];
    const float* h_b1   = (const float*)d_in[24];
    const float* h_w2   = (const float*)d_in[25];
    const float* h_b2   = (const float*)d_in[26];
    const float* h_w3   = (const float*)d_in[27];
    const float* h_b3   = (const float*)d_in[28];
    float* out = (float*)d_out;

    int smem_input = (INDIM * HH + 32 * INDIM) * 4;          // 131200
    int smem_sage  = (2 * HH * HH + 2 * 32 * HH) * 4;        // 163840
    cudaFuncSetAttribute(k_input, cudaFuncAttributeMaxDynamicSharedMemorySize, smem_input);
    cudaFuncSetAttribute(k_sage,  cudaFuncAttributeMaxDynamicSharedMemorySize, smem_sage);
    cudaFuncSetAttribute(k_passA, cudaFuncAttributeMaxDynamicSharedMemorySize, 50240);

    k_zero<<<(CC * HH + 255) / 256, 256>>>();
    k_deg<<<(ME + 255) / 256, 256>>>(edge_index);
    k_scan1<<<98, 1024>>>();
    k_scan2<<<1, 128>>>(98);
    k_scan3<<<(NN + 255) / 256, 256>>>();
    k_fill<<<(ME + 255) / 256, 256>>>(edge_index);
    k_input<<<(NN + 31) / 32, 512, smem_input>>>(
        node_feat, node_opcode, topo_depth, opcode_embed, in_w, in_b, in_g, in_beta);
    for (int l = 0; l < 4; l++) {
        k_aggregate<<<NN / 8, 256>>>();
        k_sage<<<(NN + 31) / 32, 512, smem_sage>>>(
            sage_Wl + (size_t)l * HH * HH, sage_bl + l * HH,
            sage_Wr + (size_t)l * HH * HH, ln_g + l * HH, ln_b + l * HH);
    }
    k_gmean<<<250, 256>>>();
    dim3 ga(4, 1000);
    k_passA<<<ga, 256, 50240>>>(config_ids, config_feat, cfg_w, cfg_b,
                                se_w1, se_b1, se_w2, se_b2);
    k_passB<<<320, 512>>>(temperature);
    k_head<<<CC, 128>>>(h_w1, h_b1, h_w2, h_b2, h_w3, h_b3, out);
}